// round 5
// baseline (speedup 1.0000x reference)
#include <cuda_runtime.h>
#include <cstdint>
#include <cstddef>

#define HID   1024
#define NG    4096
#define BATCH 32
#define TT    512
#define NCTA  128

// ---------------- device scratch (allocation-free) ----------------
__device__ float g_xg[(size_t)TT * BATCH * NG];   // [t*32+b][4H] precomputed input gates
__device__ float g_xr[(size_t)TT * BATCH * HID];  // x, tf32-rounded, row m = t*32+b
__device__ float g_wr[(size_t)NG * HID];          // w_ih, tf32-rounded
__device__ float g_h[2][BATCH * HID];             // ping-pong hidden state
__device__ unsigned g_bar;                        // grid barrier ticket

// ---------------- helpers ----------------
__device__ __forceinline__ float tf32r(float x) {
    unsigned u;
    asm("cvt.rna.tf32.f32 %0, %1;" : "=r"(u) : "f"(x));
    return __uint_as_float(u);
}

__device__ __forceinline__ void mma8(float* d, const unsigned* a, const unsigned* b) {
    asm volatile(
        "mma.sync.aligned.m16n8k8.row.col.f32.tf32.tf32.f32 "
        "{%0,%1,%2,%3}, {%4,%5,%6,%7}, {%8,%9}, {%0,%1,%2,%3};\n"
        : "+f"(d[0]), "+f"(d[1]), "+f"(d[2]), "+f"(d[3])
        : "r"(a[0]), "r"(a[1]), "r"(a[2]), "r"(a[3]), "r"(b[0]), "r"(b[1]));
}

__device__ __forceinline__ float sigm(float x) {
    return 1.f / (1.f + __expf(-x));
}

// ---------------- prep: round to tf32, reorder x rows to m = t*32+b ----------------
__global__ void k_prep_x(const float4* __restrict__ x) {
    size_t i = (size_t)blockIdx.x * 256 + threadIdx.x;  // over 4,194,304 float4
    int hq  = (int)(i & 255);
    int row = (int)(i >> 8);       // = b*512 + t
    int b   = row >> 9;
    int t   = row & 511;
    float4 v = x[i];
    v.x = tf32r(v.x); v.y = tf32r(v.y); v.z = tf32r(v.z); v.w = tf32r(v.w);
    ((float4*)g_xr)[((size_t)(t * 32 + b) << 8) + hq] = v;
}

__global__ void k_prep_w(const float4* __restrict__ w) {
    size_t i = (size_t)blockIdx.x * 256 + threadIdx.x;  // over 1,048,576 float4
    float4 v = w[i];
    v.x = tf32r(v.x); v.y = tf32r(v.y); v.z = tf32r(v.z); v.w = tf32r(v.w);
    ((float4*)g_wr)[i] = v;
}

__global__ void k_zero_h() {
    g_h[0][blockIdx.x * 256 + threadIdx.x] = 0.f;  // 128 blocks x 256 = 32768
}

__global__ void k_reset_bar() { g_bar = 0u; }

// ---------------- Phase 1: xg = x' @ w_ih^T + b_ih + b_hh ----------------
// M=16384 (m = t*32+b), N=4096, K=1024. BM=128, BN=64, BK=32, 256 thr.
// smem floats: A[2][128][36] then B[2][64][36]; pad 36 => conflict-free frag LDS.

__device__ __forceinline__ void p1_load(uint32_t sb, int s, int m0, int n0, int k0, int tid) {
    #pragma unroll
    for (int i = 0; i < 4; i++) {
        int ch = tid + i * 256;
        int row = ch >> 3, cq = ch & 7;
        uint32_t so = sb + (uint32_t)((s * 4608 + row * 36 + cq * 4) * 4);
        const float* gp = g_xr + (size_t)(m0 + row) * HID + k0 + cq * 4;
        asm volatile("cp.async.cg.shared.global [%0], [%1], 16;" :: "r"(so), "l"(gp));
    }
    #pragma unroll
    for (int i = 0; i < 2; i++) {
        int ch = tid + i * 256;
        int row = ch >> 3, cq = ch & 7;
        uint32_t so = sb + (uint32_t)((9216 + s * 2304 + row * 36 + cq * 4) * 4);
        const float* gp = g_wr + (size_t)(n0 + row) * HID + k0 + cq * 4;
        asm volatile("cp.async.cg.shared.global [%0], [%1], 16;" :: "r"(so), "l"(gp));
    }
    asm volatile("cp.async.commit_group;" ::: "memory");
}

__global__ void __launch_bounds__(256) k_gemm(const float* __restrict__ bih,
                                              const float* __restrict__ bhh) {
    extern __shared__ float sm[];
    const int tid  = threadIdx.x;
    const int lane = tid & 31, w = tid >> 5;
    const int wm = w >> 1, wn = w & 1;
    const int g = lane >> 2, tg = lane & 3;
    const int m0 = blockIdx.x * 128;
    const int n0 = blockIdx.y * 64;
    uint32_t sb = (uint32_t)__cvta_generic_to_shared(sm);

    float acc[2][4][4];
    #pragma unroll
    for (int mt = 0; mt < 2; mt++)
        #pragma unroll
        for (int nt = 0; nt < 4; nt++)
            #pragma unroll
            for (int r = 0; r < 4; r++) acc[mt][nt][r] = 0.f;

    p1_load(sb, 0, m0, n0, 0, tid);
    int s = 0;
    for (int it = 0; it < 32; ++it) {
        if (it + 1 < 32) p1_load(sb, s ^ 1, m0, n0, (it + 1) * 32, tid);
        else asm volatile("cp.async.commit_group;" ::: "memory");
        asm volatile("cp.async.wait_group 1;" ::: "memory");
        __syncthreads();

        const unsigned* A = (const unsigned*)(sm + s * 4608);
        const unsigned* B = (const unsigned*)(sm + 9216 + s * 2304);
        #pragma unroll
        for (int ks = 0; ks < 4; ks++) {
            unsigned a[2][4], bf[4][2];
            #pragma unroll
            for (int mt = 0; mt < 2; mt++) {
                int r = wm * 32 + mt * 16 + g;
                int col = ks * 8 + tg;
                a[mt][0] = A[r * 36 + col];
                a[mt][1] = A[(r + 8) * 36 + col];
                a[mt][2] = A[r * 36 + col + 4];
                a[mt][3] = A[(r + 8) * 36 + col + 4];
            }
            #pragma unroll
            for (int nt = 0; nt < 4; nt++) {
                int r = wn * 32 + nt * 8 + g;
                int col = ks * 8 + tg;
                bf[nt][0] = B[r * 36 + col];
                bf[nt][1] = B[r * 36 + col + 4];
            }
            #pragma unroll
            for (int mt = 0; mt < 2; mt++)
                #pragma unroll
                for (int nt = 0; nt < 4; nt++)
                    mma8(acc[mt][nt], a[mt], bf[nt]);
        }
        __syncthreads();
        s ^= 1;
    }

    // epilogue: add biases, store to g_xg[m][n]
    #pragma unroll
    for (int mt = 0; mt < 2; mt++) {
        #pragma unroll
        for (int nt = 0; nt < 4; nt++) {
            int n = n0 + wn * 32 + nt * 8 + 2 * tg;
            float b0 = bih[n] + bhh[n];
            float b1 = bih[n + 1] + bhh[n + 1];
            int ma = m0 + wm * 32 + mt * 16 + g;
            float2 v0 = make_float2(acc[mt][nt][0] + b0, acc[mt][nt][1] + b1);
            float2 v1 = make_float2(acc[mt][nt][2] + b0, acc[mt][nt][3] + b1);
            *(float2*)&g_xg[(size_t)ma * NG + n]       = v0;
            *(float2*)&g_xg[(size_t)(ma + 8) * NG + n] = v1;
        }
    }
}

// ---------------- Phase 2: persistent recurrence ----------------
// 128 CTAs x 256 threads. CTA j owns hidden n0=j*8..j*8+7 -> 32 w_hh rows
// resident in smem (tf32, pad-1028 rows). Per step: 8-warp K-split 32x32x1024
// mma, smem reduce, per-thread (b,n) cell update with c in register.
// smem floats: Ws[32][1028] then red[8][32][33]  => 165376 bytes.

__global__ void __launch_bounds__(256) k_recur(const float* __restrict__ whh,
                                               float* __restrict__ out) {
    extern __shared__ float sm[];
    float* Ws  = sm;                 // 32*1028
    float* red = sm + 32 * 1028;     // 8*32*33
    const int tid  = threadIdx.x;
    const int lane = tid & 31, w = tid >> 5;
    const int g = lane >> 2, tg = lane & 3;
    const int n0 = blockIdx.x * 8;

    // load this CTA's 32 w_hh rows (gate-major local r = gate*8 + j), tf32-rounded
    for (int i = tid; i < 32 * 1024; i += 256) {
        int r = i >> 10, k = i & 1023;
        int grow = (r >> 3) * HID + n0 + (r & 7);
        Ws[r * 1028 + k] = tf32r(whh[(size_t)grow * HID + k]);
    }
    __syncthreads();

    const unsigned* Wu = (const unsigned*)Ws;
    const int kw = w * 128;          // this warp's K slice
    const int eb = tid >> 3;         // batch index for epilogue
    const int en = tid & 7;          // local hidden index for epilogue

    float c = 0.f;
    unsigned epoch = 0;

    for (int t = 0; t < TT; ++t) {
        const float* __restrict__ hcur = g_h[t & 1];

        // prefetch this thread's input-gate values (streaming from DRAM)
        const float* xp = g_xg + ((size_t)t * 32 + eb) * NG + n0 + en;
        float xi = __ldcs(xp);
        float xf = __ldcs(xp + 1024);
        float xgt = __ldcs(xp + 2048);
        float xo = __ldcs(xp + 3072);

        float acc[2][4][4];
        #pragma unroll
        for (int mt = 0; mt < 2; mt++)
            #pragma unroll
            for (int nt = 0; nt < 4; nt++)
                #pragma unroll
                for (int r = 0; r < 4; r++) acc[mt][nt][r] = 0.f;

        #pragma unroll
        for (int ks = 0; ks < 16; ++ks) {
            int k0 = kw + ks * 8;
            unsigned a[2][4];
            #pragma unroll
            for (int mt = 0; mt < 2; mt++) {
                int r = mt * 16 + g;
                a[mt][0] = Wu[r * 1028 + k0 + tg];
                a[mt][1] = Wu[(r + 8) * 1028 + k0 + tg];
                a[mt][2] = Wu[r * 1028 + k0 + tg + 4];
                a[mt][3] = Wu[(r + 8) * 1028 + k0 + tg + 4];
            }
            #pragma unroll
            for (int nt = 0; nt < 4; nt++) {
                unsigned bf[2];
                bf[0] = __float_as_uint(__ldcg(hcur + (nt * 8 + g) * HID + k0 + tg));
                bf[1] = __float_as_uint(__ldcg(hcur + (nt * 8 + g) * HID + k0 + tg + 4));
                mma8(acc[0][nt], a[0], bf);
                mma8(acc[1][nt], a[1], bf);
            }
        }

        // D[r][b] partials -> smem
        #pragma unroll
        for (int mt = 0; mt < 2; mt++) {
            #pragma unroll
            for (int nt = 0; nt < 4; nt++) {
                int r = mt * 16 + g, b = nt * 8 + 2 * tg;
                red[(w * 32 + r) * 33 + b]         = acc[mt][nt][0];
                red[(w * 32 + r) * 33 + b + 1]     = acc[mt][nt][1];
                red[(w * 32 + r + 8) * 33 + b]     = acc[mt][nt][2];
                red[(w * 32 + r + 8) * 33 + b + 1] = acc[mt][nt][3];
            }
        }
        __syncthreads();

        // reduce 8 warps + cell update (thread -> (eb, en))
        float si = 0.f, sf = 0.f, sg = 0.f, so = 0.f;
        #pragma unroll
        for (int ww = 0; ww < 8; ww++) {
            si += red[(ww * 32 + en) * 33 + eb];
            sf += red[(ww * 32 + 8 + en) * 33 + eb];
            sg += red[(ww * 32 + 16 + en) * 33 + eb];
            so += red[(ww * 32 + 24 + en) * 33 + eb];
        }
        float gi = sigm(si + xi);
        float gf = sigm(sf + xf);
        float gg = tanhf(sg + xgt);
        float go = sigm(so + xo);
        c = gf * c + gi * gg;
        float h = go * tanhf(c);

        g_h[(t & 1) ^ 1][eb * HID + n0 + en] = tf32r(h);
        if (t == TT - 1) out[eb * HID + n0 + en] = h;

        __threadfence();
        __syncthreads();
        if (tid == 0) {
            atomicAdd(&g_bar, 1u);
            epoch += NCTA;
            while (*(volatile unsigned*)&g_bar < epoch) { }
        }
        __syncthreads();
    }
}

// ---------------- launch ----------------
extern "C" void kernel_launch(void* const* d_in, const int* in_sizes, int n_in,
                              void* d_out, int out_size) {
    const float* x   = (const float*)d_in[0];
    const float* wih = (const float*)d_in[1];
    const float* whh = (const float*)d_in[2];
    const float* bih = (const float*)d_in[3];
    const float* bhh = (const float*)d_in[4];
    float* out = (float*)d_out;

    cudaFuncSetAttribute(k_gemm,  cudaFuncAttributeMaxDynamicSharedMemorySize, 55296);
    cudaFuncSetAttribute(k_recur, cudaFuncAttributeMaxDynamicSharedMemorySize, 165376);

    k_prep_x<<<16384, 256>>>((const float4*)x);
    k_prep_w<<<4096, 256>>>((const float4*)wih);
    k_zero_h<<<128, 256>>>();
    k_reset_bar<<<1, 1>>>();

    dim3 gg(128, 64);
    k_gemm<<<gg, 256, 55296>>>(bih, bhh);
    k_recur<<<NCTA, 256, 165376>>>(whh, out);
}

// round 6
// speedup vs baseline: 1.2717x; 1.2717x over previous
#include <cuda_runtime.h>
#include <cstdint>
#include <cstddef>

#define HID   1024
#define NG    4096
#define BATCH 32
#define TT    512
#define NCTA  128

// ---------------- device scratch (allocation-free) ----------------
__device__ float g_xg[(size_t)TT * BATCH * NG];   // [t*32+b][4H] precomputed input gates
__device__ float g_xr[(size_t)TT * BATCH * HID];  // x, tf32-rounded, row m = t*32+b
__device__ float g_wr[(size_t)NG * HID];          // w_ih, tf32-rounded
__device__ float g_h[2][BATCH * HID];             // ping-pong hidden state
__device__ unsigned g_bar;                        // grid barrier ticket

// ---------------- helpers ----------------
__device__ __forceinline__ float tf32r(float x) {
    unsigned u;
    asm("cvt.rna.tf32.f32 %0, %1;" : "=r"(u) : "f"(x));
    return __uint_as_float(u);
}

__device__ __forceinline__ void mma8(float* d, const unsigned* a, const unsigned* b) {
    asm volatile(
        "mma.sync.aligned.m16n8k8.row.col.f32.tf32.tf32.f32 "
        "{%0,%1,%2,%3}, {%4,%5,%6,%7}, {%8,%9}, {%0,%1,%2,%3};\n"
        : "+f"(d[0]), "+f"(d[1]), "+f"(d[2]), "+f"(d[3])
        : "r"(a[0]), "r"(a[1]), "r"(a[2]), "r"(a[3]), "r"(b[0]), "r"(b[1]));
}

__device__ __forceinline__ float sigm(float x) {
    return 1.f / (1.f + __expf(-x));
}

// ---------------- prep: round to tf32, reorder x rows to m = t*32+b ----------------
__global__ void k_prep_x(const float4* __restrict__ x) {
    size_t i = (size_t)blockIdx.x * 256 + threadIdx.x;  // over 4,194,304 float4
    int hq  = (int)(i & 255);
    int row = (int)(i >> 8);       // = b*512 + t
    int b   = row >> 9;
    int t   = row & 511;
    float4 v = x[i];
    v.x = tf32r(v.x); v.y = tf32r(v.y); v.z = tf32r(v.z); v.w = tf32r(v.w);
    ((float4*)g_xr)[((size_t)(t * 32 + b) << 8) + hq] = v;
}

__global__ void k_prep_w(const float4* __restrict__ w) {
    size_t i = (size_t)blockIdx.x * 256 + threadIdx.x;  // over 1,048,576 float4
    float4 v = w[i];
    v.x = tf32r(v.x); v.y = tf32r(v.y); v.z = tf32r(v.z); v.w = tf32r(v.w);
    ((float4*)g_wr)[i] = v;
}

__global__ void k_zero_h() {
    g_h[0][blockIdx.x * 256 + threadIdx.x] = 0.f;  // 128 blocks x 256 = 32768
}

__global__ void k_reset_bar() { g_bar = 0u; }

// ---------------- Phase 1: xg = x' @ w_ih^T + b_ih + b_hh ----------------
// M=16384 (m = t*32+b), N=4096, K=1024. BM=128, BN=64, BK=32, 256 thr.
// smem floats: A[2][128][36] then B[2][64][36]; pad 36 => conflict-free frag LDS.

__device__ __forceinline__ void p1_load(uint32_t sb, int s, int m0, int n0, int k0, int tid) {
    #pragma unroll
    for (int i = 0; i < 4; i++) {
        int ch = tid + i * 256;
        int row = ch >> 3, cq = ch & 7;
        uint32_t so = sb + (uint32_t)((s * 4608 + row * 36 + cq * 4) * 4);
        const float* gp = g_xr + (size_t)(m0 + row) * HID + k0 + cq * 4;
        asm volatile("cp.async.cg.shared.global [%0], [%1], 16;" :: "r"(so), "l"(gp));
    }
    #pragma unroll
    for (int i = 0; i < 2; i++) {
        int ch = tid + i * 256;
        int row = ch >> 3, cq = ch & 7;
        uint32_t so = sb + (uint32_t)((9216 + s * 2304 + row * 36 + cq * 4) * 4);
        const float* gp = g_wr + (size_t)(n0 + row) * HID + k0 + cq * 4;
        asm volatile("cp.async.cg.shared.global [%0], [%1], 16;" :: "r"(so), "l"(gp));
    }
    asm volatile("cp.async.commit_group;" ::: "memory");
}

__global__ void __launch_bounds__(256) k_gemm(const float* __restrict__ bih,
                                              const float* __restrict__ bhh) {
    extern __shared__ float sm[];
    const int tid  = threadIdx.x;
    const int lane = tid & 31, w = tid >> 5;
    const int wm = w >> 1, wn = w & 1;
    const int g = lane >> 2, tg = lane & 3;
    const int m0 = blockIdx.x * 128;
    const int n0 = blockIdx.y * 64;
    uint32_t sb = (uint32_t)__cvta_generic_to_shared(sm);

    float acc[2][4][4];
    #pragma unroll
    for (int mt = 0; mt < 2; mt++)
        #pragma unroll
        for (int nt = 0; nt < 4; nt++)
            #pragma unroll
            for (int r = 0; r < 4; r++) acc[mt][nt][r] = 0.f;

    p1_load(sb, 0, m0, n0, 0, tid);
    int s = 0;
    for (int it = 0; it < 32; ++it) {
        if (it + 1 < 32) p1_load(sb, s ^ 1, m0, n0, (it + 1) * 32, tid);
        else asm volatile("cp.async.commit_group;" ::: "memory");
        asm volatile("cp.async.wait_group 1;" ::: "memory");
        __syncthreads();

        const unsigned* A = (const unsigned*)(sm + s * 4608);
        const unsigned* B = (const unsigned*)(sm + 9216 + s * 2304);
        #pragma unroll
        for (int ks = 0; ks < 4; ks++) {
            unsigned a[2][4], bf[4][2];
            #pragma unroll
            for (int mt = 0; mt < 2; mt++) {
                int r = wm * 32 + mt * 16 + g;
                int col = ks * 8 + tg;
                a[mt][0] = A[r * 36 + col];
                a[mt][1] = A[(r + 8) * 36 + col];
                a[mt][2] = A[r * 36 + col + 4];
                a[mt][3] = A[(r + 8) * 36 + col + 4];
            }
            #pragma unroll
            for (int nt = 0; nt < 4; nt++) {
                int r = wn * 32 + nt * 8 + g;
                int col = ks * 8 + tg;
                bf[nt][0] = B[r * 36 + col];
                bf[nt][1] = B[r * 36 + col + 4];
            }
            #pragma unroll
            for (int mt = 0; mt < 2; mt++)
                #pragma unroll
                for (int nt = 0; nt < 4; nt++)
                    mma8(acc[mt][nt], a[mt], bf[nt]);
        }
        __syncthreads();
        s ^= 1;
    }

    // epilogue: add biases, store to g_xg[m][n]
    #pragma unroll
    for (int mt = 0; mt < 2; mt++) {
        #pragma unroll
        for (int nt = 0; nt < 4; nt++) {
            int n = n0 + wn * 32 + nt * 8 + 2 * tg;
            float b0 = bih[n] + bhh[n];
            float b1 = bih[n + 1] + bhh[n + 1];
            int ma = m0 + wm * 32 + mt * 16 + g;
            float2 v0 = make_float2(acc[mt][nt][0] + b0, acc[mt][nt][1] + b1);
            float2 v1 = make_float2(acc[mt][nt][2] + b0, acc[mt][nt][3] + b1);
            *(float2*)&g_xg[(size_t)ma * NG + n]       = v0;
            *(float2*)&g_xg[(size_t)(ma + 8) * NG + n] = v1;
        }
    }
}

// ---------------- Phase 2: persistent recurrence (v2) ----------------
// 128 CTAs x 256 threads, 1 CTA/SM. CTA j owns hidden n0=j*8..j*8+7.
// w_hh fragments live in REGISTERS (a[16][2][4], loop-invariant over t).
// Per step: h (32x1024 fp32, 128 KB) staged into smem via cp.async (coalesced,
// MLP=32), then 8-warp K-split 32x32x1024 tf32 mma with LDS B-fragments,
// smem reduce, per-thread (b,n) cell update with c in a register, grid barrier.
// smem floats: hbuf[32][1028] then red[8][32][33]  => 165376 bytes.

__global__ void __launch_bounds__(256) k_recur(const float* __restrict__ whh,
                                               float* __restrict__ out) {
    extern __shared__ float sm[];
    float* hbuf = sm;                 // 32*1028
    float* red  = sm + 32 * 1028;     // 8*32*33
    const int tid  = threadIdx.x;
    const int lane = tid & 31, w = tid >> 5;
    const int g = lane >> 2, tg = lane & 3;
    const int n0 = blockIdx.x * 8;
    const int kw = w * 128;           // this warp's K slice
    const int eb = tid >> 3;          // batch index for epilogue
    const int en = tid & 7;           // local hidden index for epilogue

    // Load this thread's w_hh A-fragments once; resident for all 512 steps.
    // local row r = gate*8 + unit -> global row (r>>3)*HID + n0 + (r&7)
    unsigned a[16][2][4];
    #pragma unroll
    for (int ks = 0; ks < 16; ks++) {
        #pragma unroll
        for (int mt = 0; mt < 2; mt++) {
            int r0 = mt * 16 + g;
            int r1 = r0 + 8;
            size_t row0 = (size_t)((r0 >> 3) * HID + n0 + (r0 & 7)) * HID;
            size_t row1 = (size_t)((r1 >> 3) * HID + n0 + (r1 & 7)) * HID;
            int k0 = kw + ks * 8 + tg;
            a[ks][mt][0] = __float_as_uint(tf32r(whh[row0 + k0]));
            a[ks][mt][1] = __float_as_uint(tf32r(whh[row1 + k0]));
            a[ks][mt][2] = __float_as_uint(tf32r(whh[row0 + k0 + 4]));
            a[ks][mt][3] = __float_as_uint(tf32r(whh[row1 + k0 + 4]));
        }
    }

    uint32_t hb = (uint32_t)__cvta_generic_to_shared(hbuf);
    const unsigned* hu = (const unsigned*)hbuf;

    float c = 0.f;
    unsigned epoch = 0;

    for (int t = 0; t < TT; ++t) {
        const float* __restrict__ hcur = g_h[t & 1];

        // prefetch this thread's input-gate values (streaming from DRAM)
        const float* xp = g_xg + ((size_t)t * 32 + eb) * NG + n0 + en;
        float xi  = __ldcs(xp);
        float xf  = __ldcs(xp + 1024);
        float xgt = __ldcs(xp + 2048);
        float xo  = __ldcs(xp + 3072);

        // stage h into smem: coalesced 16B cp.async, padded rows of 1028 floats
        #pragma unroll
        for (int i = 0; i < 32; i++) {
            int idx = tid + i * 256;          // 0..8191 float4
            int b = idx >> 8, q = idx & 255;
            uint32_t so = hb + (uint32_t)((b * 1028 + q * 4) * 4);
            const float* gp = hcur + idx * 4;
            asm volatile("cp.async.cg.shared.global [%0], [%1], 16;" :: "r"(so), "l"(gp));
        }
        asm volatile("cp.async.commit_group;" ::: "memory");
        asm volatile("cp.async.wait_group 0;" ::: "memory");
        __syncthreads();

        float acc[2][4][4];
        #pragma unroll
        for (int mt = 0; mt < 2; mt++)
            #pragma unroll
            for (int nt = 0; nt < 4; nt++)
                #pragma unroll
                for (int r = 0; r < 4; r++) acc[mt][nt][r] = 0.f;

        #pragma unroll
        for (int ks = 0; ks < 16; ++ks) {
            int k0 = kw + ks * 8 + tg;
            #pragma unroll
            for (int nt = 0; nt < 4; nt++) {
                unsigned bf[2];
                bf[0] = hu[(nt * 8 + g) * 1028 + k0];
                bf[1] = hu[(nt * 8 + g) * 1028 + k0 + 4];
                mma8(acc[0][nt], a[ks][0], bf);
                mma8(acc[1][nt], a[ks][1], bf);
            }
        }

        // D[r][b] partials -> smem
        #pragma unroll
        for (int mt = 0; mt < 2; mt++) {
            #pragma unroll
            for (int nt = 0; nt < 4; nt++) {
                int r = mt * 16 + g, b = nt * 8 + 2 * tg;
                red[(w * 32 + r) * 33 + b]         = acc[mt][nt][0];
                red[(w * 32 + r) * 33 + b + 1]     = acc[mt][nt][1];
                red[(w * 32 + r + 8) * 33 + b]     = acc[mt][nt][2];
                red[(w * 32 + r + 8) * 33 + b + 1] = acc[mt][nt][3];
            }
        }
        __syncthreads();

        // reduce 8 warps + cell update (thread -> (eb, en))
        float si = 0.f, sf = 0.f, sg = 0.f, so = 0.f;
        #pragma unroll
        for (int ww = 0; ww < 8; ww++) {
            si += red[(ww * 32 + en) * 33 + eb];
            sf += red[(ww * 32 + 8 + en) * 33 + eb];
            sg += red[(ww * 32 + 16 + en) * 33 + eb];
            so += red[(ww * 32 + 24 + en) * 33 + eb];
        }
        float gi = sigm(si + xi);
        float gf = sigm(sf + xf);
        float gg = tanhf(sg + xgt);
        float go = sigm(so + xo);
        c = gf * c + gi * gg;
        float h = go * tanhf(c);

        g_h[(t & 1) ^ 1][eb * HID + n0 + en] = tf32r(h);
        if (t == TT - 1) out[eb * HID + n0 + en] = h;

        __threadfence();
        __syncthreads();
        if (tid == 0) {
            atomicAdd(&g_bar, 1u);
            epoch += NCTA;
            while (*(volatile unsigned*)&g_bar < epoch) { }
        }
        __syncthreads();
    }
}

// ---------------- launch ----------------
extern "C" void kernel_launch(void* const* d_in, const int* in_sizes, int n_in,
                              void* d_out, int out_size) {
    const float* x   = (const float*)d_in[0];
    const float* wih = (const float*)d_in[1];
    const float* whh = (const float*)d_in[2];
    const float* bih = (const float*)d_in[3];
    const float* bhh = (const float*)d_in[4];
    float* out = (float*)d_out;

    cudaFuncSetAttribute(k_gemm,  cudaFuncAttributeMaxDynamicSharedMemorySize, 55296);
    cudaFuncSetAttribute(k_recur, cudaFuncAttributeMaxDynamicSharedMemorySize, 165376);

    k_prep_x<<<16384, 256>>>((const float4*)x);
    k_prep_w<<<4096, 256>>>((const float4*)wih);
    k_zero_h<<<128, 256>>>();
    k_reset_bar<<<1, 1>>>();

    dim3 gg(128, 64);
    k_gemm<<<gg, 256, 55296>>>(bih, bhh);
    k_recur<<<NCTA, 256, 165376>>>(whh, out);
}

// round 7
// speedup vs baseline: 1.3938x; 1.0961x over previous
#include <cuda_runtime.h>
#include <cstdint>
#include <cstddef>

#define HID   1024
#define NG    4096
#define BATCH 32
#define TT    512
#define NCTA  128

// ---------------- device scratch (allocation-free) ----------------
__device__ float g_xg[(size_t)TT * BATCH * NG];   // [t*32+b][4H] precomputed input gates
__device__ float g_xr[(size_t)TT * BATCH * HID];  // x, tf32-rounded, row m = t*32+b
__device__ float g_wr[(size_t)NG * HID];          // w_ih, tf32-rounded
__device__ float g_h[2][BATCH * HID];             // ping-pong hidden state
__device__ unsigned g_bar;                        // grid barrier ticket

// ---------------- helpers ----------------
__device__ __forceinline__ float tf32r(float x) {
    unsigned u;
    asm("cvt.rna.tf32.f32 %0, %1;" : "=r"(u) : "f"(x));
    return __uint_as_float(u);
}

__device__ __forceinline__ void mma8(float* d, const unsigned* a, const unsigned* b) {
    asm volatile(
        "mma.sync.aligned.m16n8k8.row.col.f32.tf32.tf32.f32 "
        "{%0,%1,%2,%3}, {%4,%5,%6,%7}, {%8,%9}, {%0,%1,%2,%3};\n"
        : "+f"(d[0]), "+f"(d[1]), "+f"(d[2]), "+f"(d[3])
        : "r"(a[0]), "r"(a[1]), "r"(a[2]), "r"(a[3]), "r"(b[0]), "r"(b[1]));
}

__device__ __forceinline__ float sigm(float x) {
    return 1.f / (1.f + __expf(-x));
}

// ---------------- prep: round to tf32, reorder x rows to m = t*32+b ----------------
__global__ void k_prep_x(const float4* __restrict__ x) {
    size_t i = (size_t)blockIdx.x * 256 + threadIdx.x;  // over 4,194,304 float4
    int hq  = (int)(i & 255);
    int row = (int)(i >> 8);       // = b*512 + t
    int b   = row >> 9;
    int t   = row & 511;
    float4 v = x[i];
    v.x = tf32r(v.x); v.y = tf32r(v.y); v.z = tf32r(v.z); v.w = tf32r(v.w);
    ((float4*)g_xr)[((size_t)(t * 32 + b) << 8) + hq] = v;
}

__global__ void k_prep_w(const float4* __restrict__ w) {
    size_t i = (size_t)blockIdx.x * 256 + threadIdx.x;  // over 1,048,576 float4
    float4 v = w[i];
    v.x = tf32r(v.x); v.y = tf32r(v.y); v.z = tf32r(v.z); v.w = tf32r(v.w);
    ((float4*)g_wr)[i] = v;
}

__global__ void k_zero_h() {
    g_h[0][blockIdx.x * 256 + threadIdx.x] = 0.f;  // 128 blocks x 256 = 32768
}

__global__ void k_reset_bar() { g_bar = 0u; }

// ---------------- Phase 1: xg = x' @ w_ih^T + b_ih + b_hh ----------------
// M=16384 (m = t*32+b), N=4096, K=1024. BM=128, BN=64, BK=32, 256 thr.
// smem floats: A[2][128][36] then B[2][64][36]; pad 36 => conflict-free frag LDS.

__device__ __forceinline__ void p1_load(uint32_t sb, int s, int m0, int n0, int k0, int tid) {
    #pragma unroll
    for (int i = 0; i < 4; i++) {
        int ch = tid + i * 256;
        int row = ch >> 3, cq = ch & 7;
        uint32_t so = sb + (uint32_t)((s * 4608 + row * 36 + cq * 4) * 4);
        const float* gp = g_xr + (size_t)(m0 + row) * HID + k0 + cq * 4;
        asm volatile("cp.async.cg.shared.global [%0], [%1], 16;" :: "r"(so), "l"(gp));
    }
    #pragma unroll
    for (int i = 0; i < 2; i++) {
        int ch = tid + i * 256;
        int row = ch >> 3, cq = ch & 7;
        uint32_t so = sb + (uint32_t)((9216 + s * 2304 + row * 36 + cq * 4) * 4);
        const float* gp = g_wr + (size_t)(n0 + row) * HID + k0 + cq * 4;
        asm volatile("cp.async.cg.shared.global [%0], [%1], 16;" :: "r"(so), "l"(gp));
    }
    asm volatile("cp.async.commit_group;" ::: "memory");
}

__global__ void __launch_bounds__(256) k_gemm(const float* __restrict__ bih,
                                              const float* __restrict__ bhh) {
    extern __shared__ float sm[];
    const int tid  = threadIdx.x;
    const int lane = tid & 31, w = tid >> 5;
    const int wm = w >> 1, wn = w & 1;
    const int g = lane >> 2, tg = lane & 3;
    const int m0 = blockIdx.x * 128;
    const int n0 = blockIdx.y * 64;
    uint32_t sb = (uint32_t)__cvta_generic_to_shared(sm);

    float acc[2][4][4];
    #pragma unroll
    for (int mt = 0; mt < 2; mt++)
        #pragma unroll
        for (int nt = 0; nt < 4; nt++)
            #pragma unroll
            for (int r = 0; r < 4; r++) acc[mt][nt][r] = 0.f;

    p1_load(sb, 0, m0, n0, 0, tid);
    int s = 0;
    for (int it = 0; it < 32; ++it) {
        if (it + 1 < 32) p1_load(sb, s ^ 1, m0, n0, (it + 1) * 32, tid);
        else asm volatile("cp.async.commit_group;" ::: "memory");
        asm volatile("cp.async.wait_group 1;" ::: "memory");
        __syncthreads();

        const unsigned* A = (const unsigned*)(sm + s * 4608);
        const unsigned* B = (const unsigned*)(sm + 9216 + s * 2304);
        #pragma unroll
        for (int ks = 0; ks < 4; ks++) {
            unsigned a[2][4], bf[4][2];
            #pragma unroll
            for (int mt = 0; mt < 2; mt++) {
                int r = wm * 32 + mt * 16 + g;
                int col = ks * 8 + tg;
                a[mt][0] = A[r * 36 + col];
                a[mt][1] = A[(r + 8) * 36 + col];
                a[mt][2] = A[r * 36 + col + 4];
                a[mt][3] = A[(r + 8) * 36 + col + 4];
            }
            #pragma unroll
            for (int nt = 0; nt < 4; nt++) {
                int r = wn * 32 + nt * 8 + g;
                int col = ks * 8 + tg;
                bf[nt][0] = B[r * 36 + col];
                bf[nt][1] = B[r * 36 + col + 4];
            }
            #pragma unroll
            for (int mt = 0; mt < 2; mt++)
                #pragma unroll
                for (int nt = 0; nt < 4; nt++)
                    mma8(acc[mt][nt], a[mt], bf[nt]);
        }
        __syncthreads();
        s ^= 1;
    }

    // epilogue: add biases, store to g_xg[m][n]
    #pragma unroll
    for (int mt = 0; mt < 2; mt++) {
        #pragma unroll
        for (int nt = 0; nt < 4; nt++) {
            int n = n0 + wn * 32 + nt * 8 + 2 * tg;
            float b0 = bih[n] + bhh[n];
            float b1 = bih[n + 1] + bhh[n + 1];
            int ma = m0 + wm * 32 + mt * 16 + g;
            float2 v0 = make_float2(acc[mt][nt][0] + b0, acc[mt][nt][1] + b1);
            float2 v1 = make_float2(acc[mt][nt][2] + b0, acc[mt][nt][3] + b1);
            *(float2*)&g_xg[(size_t)ma * NG + n]       = v0;
            *(float2*)&g_xg[(size_t)(ma + 8) * NG + n] = v1;
        }
    }
}

// ---------------- Phase 2: persistent recurrence (v3) ----------------
// 128 CTAs x 256 threads, 1 CTA/SM. CTA j owns hidden n0=j*8..j*8+7.
// w_hh fragments in REGISTERS (a[16][2][4], loop-invariant over t).
// Per step, WARP-PRIVATE pipelined staging: warp w copies only its K-slice of h
// (32 rows x 128 cols, stride 132 -> conflict-free) in 2 cp.async commit groups
// of 16 rows; mma on rows 0-15 overlaps the second group's transfer. No block
// sync before mma. Then smem reduce, per-thread cell update (c in register),
// grid barrier.
// smem floats: hbuf[8][32][132] (33792) then red[8][32][33] (8448) => 168960 B.

// mma over rows [nt0*8, nt0*8+16) of this warp's slice
#define P2_HALF(nt0)                                                        \
    _Pragma("unroll")                                                       \
    for (int ks = 0; ks < 16; ++ks) {                                       \
        int k0 = ks * 8 + tg;                                               \
        unsigned bf0[2], bf1[2];                                            \
        bf0[0] = hw[((nt0) * 8 + g) * 132 + k0];                            \
        bf0[1] = hw[((nt0) * 8 + g) * 132 + k0 + 4];                        \
        bf1[0] = hw[((nt0) * 8 + 8 + g) * 132 + k0];                        \
        bf1[1] = hw[((nt0) * 8 + 8 + g) * 132 + k0 + 4];                    \
        mma8(acc[0][(nt0)], a[ks][0], bf0);                                 \
        mma8(acc[1][(nt0)], a[ks][1], bf0);                                 \
        mma8(acc[0][(nt0) + 1], a[ks][0], bf1);                             \
        mma8(acc[1][(nt0) + 1], a[ks][1], bf1);                             \
    }

__global__ void __launch_bounds__(256) k_recur(const float* __restrict__ whh,
                                               float* __restrict__ out) {
    extern __shared__ float sm[];
    float* red = sm + 8 * 32 * 132;   // after per-warp h buffers
    const int tid  = threadIdx.x;
    const int lane = tid & 31, w = tid >> 5;
    const int g = lane >> 2, tg = lane & 3;
    const int n0 = blockIdx.x * 8;
    const int kw = w * 128;           // this warp's K slice
    const int eb = tid >> 3;          // batch index for epilogue
    const int en = tid & 7;           // local hidden index for epilogue

    float* hbw = sm + w * 32 * 132;   // this warp's private h slice buffer
    uint32_t hb = (uint32_t)__cvta_generic_to_shared(hbw);
    const unsigned* hw = (const unsigned*)hbw;

    // Load this thread's w_hh A-fragments once; resident for all 512 steps.
    // local row r = gate*8 + unit -> global row (r>>3)*HID + n0 + (r&7)
    unsigned a[16][2][4];
    #pragma unroll
    for (int ks = 0; ks < 16; ks++) {
        #pragma unroll
        for (int mt = 0; mt < 2; mt++) {
            int r0 = mt * 16 + g;
            int r1 = r0 + 8;
            size_t row0 = (size_t)((r0 >> 3) * HID + n0 + (r0 & 7)) * HID;
            size_t row1 = (size_t)((r1 >> 3) * HID + n0 + (r1 & 7)) * HID;
            int k0 = kw + ks * 8 + tg;
            a[ks][mt][0] = __float_as_uint(tf32r(whh[row0 + k0]));
            a[ks][mt][1] = __float_as_uint(tf32r(whh[row1 + k0]));
            a[ks][mt][2] = __float_as_uint(tf32r(whh[row0 + k0 + 4]));
            a[ks][mt][3] = __float_as_uint(tf32r(whh[row1 + k0 + 4]));
        }
    }

    float c = 0.f;
    unsigned epoch = 0;

    for (int t = 0; t < TT; ++t) {
        const float* __restrict__ hcur = g_h[t & 1];

        // prefetch this thread's input-gate values (streaming from DRAM)
        const float* xp = g_xg + ((size_t)t * 32 + eb) * NG + n0 + en;
        float xi  = __ldcs(xp);
        float xf  = __ldcs(xp + 1024);
        float xgt = __ldcs(xp + 2048);
        float xo  = __ldcs(xp + 3072);

        // stage this warp's K-slice of h: 2 commit groups of 16 rows
        #pragma unroll
        for (int half = 0; half < 2; half++) {
            #pragma unroll
            for (int j = 0; j < 16; j++) {
                int r = half * 16 + j;
                uint32_t so = hb + (uint32_t)((r * 132 + lane * 4) * 4);
                const float* gp = hcur + r * HID + kw + lane * 4;
                asm volatile("cp.async.cg.shared.global [%0], [%1], 16;" :: "r"(so), "l"(gp));
            }
            asm volatile("cp.async.commit_group;" ::: "memory");
        }

        float acc[2][4][4];
        #pragma unroll
        for (int mt = 0; mt < 2; mt++)
            #pragma unroll
            for (int nt = 0; nt < 4; nt++)
                #pragma unroll
                for (int r = 0; r < 4; r++) acc[mt][nt][r] = 0.f;

        asm volatile("cp.async.wait_group 1;" ::: "memory");
        __syncwarp();
        P2_HALF(0)
        asm volatile("cp.async.wait_group 0;" ::: "memory");
        __syncwarp();
        P2_HALF(2)

        // D[r][b] partials -> smem
        #pragma unroll
        for (int mt = 0; mt < 2; mt++) {
            #pragma unroll
            for (int nt = 0; nt < 4; nt++) {
                int r = mt * 16 + g, b = nt * 8 + 2 * tg;
                red[(w * 32 + r) * 33 + b]         = acc[mt][nt][0];
                red[(w * 32 + r) * 33 + b + 1]     = acc[mt][nt][1];
                red[(w * 32 + r + 8) * 33 + b]     = acc[mt][nt][2];
                red[(w * 32 + r + 8) * 33 + b + 1] = acc[mt][nt][3];
            }
        }
        __syncthreads();

        // reduce 8 warps + cell update (thread -> (eb, en))
        float si = 0.f, sf = 0.f, sg = 0.f, so = 0.f;
        #pragma unroll
        for (int ww = 0; ww < 8; ww++) {
            si += red[(ww * 32 + en) * 33 + eb];
            sf += red[(ww * 32 + 8 + en) * 33 + eb];
            sg += red[(ww * 32 + 16 + en) * 33 + eb];
            so += red[(ww * 32 + 24 + en) * 33 + eb];
        }
        float gi = sigm(si + xi);
        float gf = sigm(sf + xf);
        float gg = tanhf(sg + xgt);
        float go = sigm(so + xo);
        c = gf * c + gi * gg;
        float h = go * tanhf(c);

        g_h[(t & 1) ^ 1][eb * HID + n0 + en] = tf32r(h);
        if (t == TT - 1) out[eb * HID + n0 + en] = h;

        __threadfence();
        __syncthreads();
        if (tid == 0) {
            atomicAdd(&g_bar, 1u);
            epoch += NCTA;
            while (*(volatile unsigned*)&g_bar < epoch) { }
        }
        __syncthreads();
    }
}

// ---------------- launch ----------------
extern "C" void kernel_launch(void* const* d_in, const int* in_sizes, int n_in,
                              void* d_out, int out_size) {
    const float* x   = (const float*)d_in[0];
    const float* wih = (const float*)d_in[1];
    const float* whh = (const float*)d_in[2];
    const float* bih = (const float*)d_in[3];
    const float* bhh = (const float*)d_in[4];
    float* out = (float*)d_out;

    cudaFuncSetAttribute(k_gemm,  cudaFuncAttributeMaxDynamicSharedMemorySize, 55296);
    cudaFuncSetAttribute(k_recur, cudaFuncAttributeMaxDynamicSharedMemorySize, 168960);

    k_prep_x<<<16384, 256>>>((const float4*)x);
    k_prep_w<<<4096, 256>>>((const float4*)wih);
    k_zero_h<<<128, 256>>>();
    k_reset_bar<<<1, 1>>>();

    dim3 gg(128, 64);
    k_gemm<<<gg, 256, 55296>>>(bih, bhh);
    k_recur<<<NCTA, 256, 168960>>>(whh, out);
}

// round 8
// speedup vs baseline: 1.5383x; 1.1036x over previous
#include <cuda_runtime.h>
#include <cstdint>
#include <cstddef>

#define HID   1024
#define NG    4096
#define BATCH 32
#define TT    512
#define NCTA  128

// ---------------- device scratch (allocation-free) ----------------
__device__ float g_xg[(size_t)TT * BATCH * NG];   // [t*32+b][4H] precomputed input gates
__device__ float g_xr[(size_t)TT * BATCH * HID];  // x, tf32-rounded, row m = t*32+b
__device__ float g_wr[(size_t)NG * HID];          // w_ih, tf32-rounded
__device__ float g_h[2][BATCH * HID];             // ping-pong hidden state
__device__ unsigned g_bar;                        // grid barrier ticket

// ---------------- helpers ----------------
__device__ __forceinline__ float tf32r(float x) {
    unsigned u;
    asm("cvt.rna.tf32.f32 %0, %1;" : "=r"(u) : "f"(x));
    return __uint_as_float(u);
}

__device__ __forceinline__ void mma8(float* d, const unsigned* a, const unsigned* b) {
    asm volatile(
        "mma.sync.aligned.m16n8k8.row.col.f32.tf32.tf32.f32 "
        "{%0,%1,%2,%3}, {%4,%5,%6,%7}, {%8,%9}, {%0,%1,%2,%3};\n"
        : "+f"(d[0]), "+f"(d[1]), "+f"(d[2]), "+f"(d[3])
        : "r"(a[0]), "r"(a[1]), "r"(a[2]), "r"(a[3]), "r"(b[0]), "r"(b[1]));
}

__device__ __forceinline__ float sigm(float x) {
    return 1.f / (1.f + __expf(-x));
}

// ---------------- fused prep: round to tf32; reorder x rows to m = t*32+b ----------------
// grid = 20480 blocks: first 16384 handle x (4,194,304 float4), rest handle w_ih.
__global__ void k_prep(const float4* __restrict__ x, const float4* __restrict__ w) {
    if (blockIdx.x < 16384) {
        size_t i = (size_t)blockIdx.x * 256 + threadIdx.x;
        int hq  = (int)(i & 255);
        int row = (int)(i >> 8);       // = b*512 + t
        int b   = row >> 9;
        int t   = row & 511;
        float4 v = x[i];
        v.x = tf32r(v.x); v.y = tf32r(v.y); v.z = tf32r(v.z); v.w = tf32r(v.w);
        ((float4*)g_xr)[((size_t)(t * 32 + b) << 8) + hq] = v;
    } else {
        size_t i = (size_t)(blockIdx.x - 16384) * 256 + threadIdx.x;  // over 1,048,576 float4
        float4 v = w[i];
        v.x = tf32r(v.x); v.y = tf32r(v.y); v.z = tf32r(v.z); v.w = tf32r(v.w);
        ((float4*)g_wr)[i] = v;
    }
}

// fused init: zero h[0] + reset barrier ticket
__global__ void k_init() {
    g_h[0][blockIdx.x * 256 + threadIdx.x] = 0.f;  // 128 x 256 = 32768
    if (blockIdx.x == 0 && threadIdx.x == 0) g_bar = 0u;
}

// ---------------- Phase 1: xg = x' @ w_ih^T + b_ih + b_hh ----------------
// M=16384 (m = t*32+b), N=4096, K=1024. BM=128, BN=64, BK=32, 256 thr.
// smem floats: A[2][128][36] then B[2][64][36]; pad 36 => conflict-free frag LDS.

__device__ __forceinline__ void p1_load(uint32_t sb, int s, int m0, int n0, int k0, int tid) {
    #pragma unroll
    for (int i = 0; i < 4; i++) {
        int ch = tid + i * 256;
        int row = ch >> 3, cq = ch & 7;
        uint32_t so = sb + (uint32_t)((s * 4608 + row * 36 + cq * 4) * 4);
        const float* gp = g_xr + (size_t)(m0 + row) * HID + k0 + cq * 4;
        asm volatile("cp.async.cg.shared.global [%0], [%1], 16;" :: "r"(so), "l"(gp));
    }
    #pragma unroll
    for (int i = 0; i < 2; i++) {
        int ch = tid + i * 256;
        int row = ch >> 3, cq = ch & 7;
        uint32_t so = sb + (uint32_t)((9216 + s * 2304 + row * 36 + cq * 4) * 4);
        const float* gp = g_wr + (size_t)(n0 + row) * HID + k0 + cq * 4;
        asm volatile("cp.async.cg.shared.global [%0], [%1], 16;" :: "r"(so), "l"(gp));
    }
    asm volatile("cp.async.commit_group;" ::: "memory");
}

__global__ void __launch_bounds__(256) k_gemm(const float* __restrict__ bih,
                                              const float* __restrict__ bhh) {
    extern __shared__ float sm[];
    const int tid  = threadIdx.x;
    const int lane = tid & 31, w = tid >> 5;
    const int wm = w >> 1, wn = w & 1;
    const int g = lane >> 2, tg = lane & 3;
    const int m0 = blockIdx.x * 128;
    const int n0 = blockIdx.y * 64;
    uint32_t sb = (uint32_t)__cvta_generic_to_shared(sm);

    float acc[2][4][4];
    #pragma unroll
    for (int mt = 0; mt < 2; mt++)
        #pragma unroll
        for (int nt = 0; nt < 4; nt++)
            #pragma unroll
            for (int r = 0; r < 4; r++) acc[mt][nt][r] = 0.f;

    p1_load(sb, 0, m0, n0, 0, tid);
    int s = 0;
    for (int it = 0; it < 32; ++it) {
        if (it + 1 < 32) p1_load(sb, s ^ 1, m0, n0, (it + 1) * 32, tid);
        else asm volatile("cp.async.commit_group;" ::: "memory");
        asm volatile("cp.async.wait_group 1;" ::: "memory");
        __syncthreads();

        const unsigned* A = (const unsigned*)(sm + s * 4608);
        const unsigned* B = (const unsigned*)(sm + 9216 + s * 2304);
        #pragma unroll
        for (int ks = 0; ks < 4; ks++) {
            unsigned a[2][4], bf[4][2];
            #pragma unroll
            for (int mt = 0; mt < 2; mt++) {
                int r = wm * 32 + mt * 16 + g;
                int col = ks * 8 + tg;
                a[mt][0] = A[r * 36 + col];
                a[mt][1] = A[(r + 8) * 36 + col];
                a[mt][2] = A[r * 36 + col + 4];
                a[mt][3] = A[(r + 8) * 36 + col + 4];
            }
            #pragma unroll
            for (int nt = 0; nt < 4; nt++) {
                int r = wn * 32 + nt * 8 + g;
                int col = ks * 8 + tg;
                bf[nt][0] = B[r * 36 + col];
                bf[nt][1] = B[r * 36 + col + 4];
            }
            #pragma unroll
            for (int mt = 0; mt < 2; mt++)
                #pragma unroll
                for (int nt = 0; nt < 4; nt++)
                    mma8(acc[mt][nt], a[mt], bf[nt]);
        }
        __syncthreads();
        s ^= 1;
    }

    // epilogue: add biases, store to g_xg[m][n]
    #pragma unroll
    for (int mt = 0; mt < 2; mt++) {
        #pragma unroll
        for (int nt = 0; nt < 4; nt++) {
            int n = n0 + wn * 32 + nt * 8 + 2 * tg;
            float b0 = bih[n] + bhh[n];
            float b1 = bih[n + 1] + bhh[n + 1];
            int ma = m0 + wm * 32 + mt * 16 + g;
            float2 v0 = make_float2(acc[mt][nt][0] + b0, acc[mt][nt][1] + b1);
            float2 v1 = make_float2(acc[mt][nt][2] + b0, acc[mt][nt][3] + b1);
            *(float2*)&g_xg[(size_t)ma * NG + n]       = v0;
            *(float2*)&g_xg[(size_t)(ma + 8) * NG + n] = v1;
        }
    }
}

// ---------------- Phase 2: persistent recurrence (v4) ----------------
// 128 CTAs x 256 threads, 1 CTA/SM. CTA j owns hidden n0=j*8..j*8+7.
// w_hh fragments in REGISTERS (a[16][2][4], loop-invariant over t).
// Per step: warp-private h K-slice staged via cp.async in 4 commit groups of
// 8 rows (stride 132 -> conflict-free); mma on rows 0-15 overlaps the rest.
// smem reduce (pad 36 -> conflict-free reads), per-thread cell update with c
// in a register, release/acquire grid barrier (no full threadfence).
// smem floats: hbuf[8][32][132] (135168 B) then red[8][32][36] (36864 B).

#define P2_HALF(nt0)                                                        \
    _Pragma("unroll")                                                       \
    for (int ks = 0; ks < 16; ++ks) {                                       \
        int k0 = ks * 8 + tg;                                               \
        unsigned bf0[2], bf1[2];                                            \
        bf0[0] = hw[((nt0) * 8 + g) * 132 + k0];                            \
        bf0[1] = hw[((nt0) * 8 + g) * 132 + k0 + 4];                        \
        bf1[0] = hw[((nt0) * 8 + 8 + g) * 132 + k0];                        \
        bf1[1] = hw[((nt0) * 8 + 8 + g) * 132 + k0 + 4];                    \
        mma8(acc[0][(nt0)], a[ks][0], bf0);                                 \
        mma8(acc[1][(nt0)], a[ks][1], bf0);                                 \
        mma8(acc[0][(nt0) + 1], a[ks][0], bf1);                             \
        mma8(acc[1][(nt0) + 1], a[ks][1], bf1);                             \
    }

__global__ void __launch_bounds__(256) k_recur(const float* __restrict__ whh,
                                               float* __restrict__ out) {
    extern __shared__ float sm[];
    float* red = sm + 8 * 32 * 132;   // after per-warp h buffers
    const int tid  = threadIdx.x;
    const int lane = tid & 31, w = tid >> 5;
    const int g = lane >> 2, tg = lane & 3;
    const int n0 = blockIdx.x * 8;
    const int kw = w * 128;           // this warp's K slice
    const int eb = tid >> 3;          // batch index for epilogue
    const int en = tid & 7;           // local hidden index for epilogue

    float* hbw = sm + w * 32 * 132;   // this warp's private h slice buffer
    uint32_t hb = (uint32_t)__cvta_generic_to_shared(hbw);
    const unsigned* hw = (const unsigned*)hbw;

    // Load this thread's w_hh A-fragments once; resident for all 512 steps.
    // local row r = gate*8 + unit -> global row (r>>3)*HID + n0 + (r&7)
    unsigned a[16][2][4];
    #pragma unroll
    for (int ks = 0; ks < 16; ks++) {
        #pragma unroll
        for (int mt = 0; mt < 2; mt++) {
            int r0 = mt * 16 + g;
            int r1 = r0 + 8;
            size_t row0 = (size_t)((r0 >> 3) * HID + n0 + (r0 & 7)) * HID;
            size_t row1 = (size_t)((r1 >> 3) * HID + n0 + (r1 & 7)) * HID;
            int k0 = kw + ks * 8 + tg;
            a[ks][mt][0] = __float_as_uint(tf32r(whh[row0 + k0]));
            a[ks][mt][1] = __float_as_uint(tf32r(whh[row1 + k0]));
            a[ks][mt][2] = __float_as_uint(tf32r(whh[row0 + k0 + 4]));
            a[ks][mt][3] = __float_as_uint(tf32r(whh[row1 + k0 + 4]));
        }
    }

    float c = 0.f;
    unsigned epoch = 0;

    for (int t = 0; t < TT; ++t) {
        const float* __restrict__ hcur = g_h[t & 1];

        // prefetch this thread's input-gate values (streaming from DRAM)
        const float* xp = g_xg + ((size_t)t * 32 + eb) * NG + n0 + en;
        float xi  = __ldcs(xp);
        float xf  = __ldcs(xp + 1024);
        float xgt = __ldcs(xp + 2048);
        float xo  = __ldcs(xp + 3072);

        // stage this warp's K-slice of h: 4 commit groups of 8 rows
        #pragma unroll
        for (int q = 0; q < 4; q++) {
            #pragma unroll
            for (int j = 0; j < 8; j++) {
                int r = q * 8 + j;
                uint32_t so = hb + (uint32_t)((r * 132 + lane * 4) * 4);
                const float* gp = hcur + r * HID + kw + lane * 4;
                asm volatile("cp.async.cg.shared.global [%0], [%1], 16;" :: "r"(so), "l"(gp));
            }
            asm volatile("cp.async.commit_group;" ::: "memory");
        }

        float acc[2][4][4];
        #pragma unroll
        for (int mt = 0; mt < 2; mt++)
            #pragma unroll
            for (int nt = 0; nt < 4; nt++)
                #pragma unroll
                for (int r = 0; r < 4; r++) acc[mt][nt][r] = 0.f;

        asm volatile("cp.async.wait_group 2;" ::: "memory");  // rows 0-15 ready
        __syncwarp();
        P2_HALF(0)
        asm volatile("cp.async.wait_group 0;" ::: "memory");  // rows 16-31 ready
        __syncwarp();
        P2_HALF(2)

        // D[r][b] partials -> smem (float2, pad 36)
        #pragma unroll
        for (int mt = 0; mt < 2; mt++) {
            #pragma unroll
            for (int nt = 0; nt < 4; nt++) {
                int r = mt * 16 + g, b = nt * 8 + 2 * tg;
                *(float2*)&red[(w * 32 + r) * 36 + b]     = make_float2(acc[mt][nt][0], acc[mt][nt][1]);
                *(float2*)&red[(w * 32 + r + 8) * 36 + b] = make_float2(acc[mt][nt][2], acc[mt][nt][3]);
            }
        }
        __syncthreads();

        // reduce 8 warps + cell update (thread -> (eb, en)); reads conflict-free
        float si = 0.f, sf = 0.f, sg = 0.f, so = 0.f;
        #pragma unroll
        for (int ww = 0; ww < 8; ww++) {
            si += red[(ww * 32 + en) * 36 + eb];
            sf += red[(ww * 32 + 8 + en) * 36 + eb];
            sg += red[(ww * 32 + 16 + en) * 36 + eb];
            so += red[(ww * 32 + 24 + en) * 36 + eb];
        }
        float gi = sigm(si + xi);
        float gf = sigm(sf + xf);
        float gg = tanhf(sg + xgt);
        float go = sigm(so + xo);
        c = gf * c + gi * gg;
        float h = go * tanhf(c);

        g_h[(t & 1) ^ 1][eb * HID + n0 + en] = tf32r(h);
        if (t == TT - 1) out[eb * HID + n0 + en] = h;

        // release/acquire grid barrier: h stores -> bar.sync -> release red ->
        // acquire spin -> bar.sync gives transitive cross-CTA visibility.
        __syncthreads();
        epoch += NCTA;
        if (tid == 0) {
            asm volatile("red.release.gpu.global.add.u32 [%0], %1;"
                         :: "l"(&g_bar), "r"(1u) : "memory");
            unsigned v;
            do {
                asm volatile("ld.acquire.gpu.global.u32 %0, [%1];"
                             : "=r"(v) : "l"(&g_bar) : "memory");
            } while (v < epoch);
        }
        __syncthreads();
    }
}

// ---------------- launch ----------------
extern "C" void kernel_launch(void* const* d_in, const int* in_sizes, int n_in,
                              void* d_out, int out_size) {
    const float* x   = (const float*)d_in[0];
    const float* wih = (const float*)d_in[1];
    const float* whh = (const float*)d_in[2];
    const float* bih = (const float*)d_in[3];
    const float* bhh = (const float*)d_in[4];
    float* out = (float*)d_out;

    cudaFuncSetAttribute(k_gemm,  cudaFuncAttributeMaxDynamicSharedMemorySize, 55296);
    cudaFuncSetAttribute(k_recur, cudaFuncAttributeMaxDynamicSharedMemorySize, 172032);

    k_prep<<<20480, 256>>>((const float4*)x, (const float4*)wih);
    k_init<<<128, 256>>>();

    dim3 gg(128, 64);
    k_gemm<<<gg, 256, 55296>>>(bih, bhh);
    k_recur<<<NCTA, 256, 172032>>>(whh, out);
}

// round 10
// speedup vs baseline: 1.5807x; 1.0276x over previous
#include <cuda_runtime.h>
#include <cstdint>
#include <cstddef>

#define HID   1024
#define NG    4096
#define BATCH 32
#define TT    512
#define NCTA  128

// ---------------- device scratch (allocation-free) ----------------
__device__ float g_xg[(size_t)TT * BATCH * NG];   // [t*32+b][4H] precomputed input gates
__device__ float g_xr[(size_t)TT * BATCH * HID];  // x, tf32-rounded, row m = t*32+b
__device__ float g_wr[(size_t)NG * HID];          // w_ih, tf32-rounded
__device__ float g_h[3][BATCH * HID];             // triple-buffered hidden state
__device__ unsigned g_flag[NCTA * 64];            // per-producer epoch flags, 256B apart

// ---------------- helpers ----------------
__device__ __forceinline__ float tf32r(float x) {
    unsigned u;
    asm("cvt.rna.tf32.f32 %0, %1;" : "=r"(u) : "f"(x));
    return __uint_as_float(u);
}

__device__ __forceinline__ void mma8(float* d, const unsigned* a, const unsigned* b) {
    asm volatile(
        "mma.sync.aligned.m16n8k8.row.col.f32.tf32.tf32.f32 "
        "{%0,%1,%2,%3}, {%4,%5,%6,%7}, {%8,%9}, {%0,%1,%2,%3};\n"
        : "+f"(d[0]), "+f"(d[1]), "+f"(d[2]), "+f"(d[3])
        : "r"(a[0]), "r"(a[1]), "r"(a[2]), "r"(a[3]), "r"(b[0]), "r"(b[1]));
}

__device__ __forceinline__ float sigm(float x) {
    return 1.f / (1.f + __expf(-x));
}

// ---------------- fused prep: round to tf32; reorder x rows to m = t*32+b ----------------
__global__ void k_prep(const float4* __restrict__ x, const float4* __restrict__ w) {
    if (blockIdx.x < 16384) {
        size_t i = (size_t)blockIdx.x * 256 + threadIdx.x;
        int hq  = (int)(i & 255);
        int row = (int)(i >> 8);       // = b*512 + t
        int b   = row >> 9;
        int t   = row & 511;
        float4 v = x[i];
        v.x = tf32r(v.x); v.y = tf32r(v.y); v.z = tf32r(v.z); v.w = tf32r(v.w);
        ((float4*)g_xr)[((size_t)(t * 32 + b) << 8) + hq] = v;
    } else {
        size_t i = (size_t)(blockIdx.x - 16384) * 256 + threadIdx.x;  // over 1,048,576 float4
        float4 v = w[i];
        v.x = tf32r(v.x); v.y = tf32r(v.y); v.z = tf32r(v.z); v.w = tf32r(v.w);
        ((float4*)g_wr)[i] = v;
    }
}

// fused init: zero h buffer 0 + reset all flags
__global__ void k_init() {
    int i = blockIdx.x * 256 + threadIdx.x;   // 128 x 256 = 32768
    g_h[0][i] = 0.f;
    if (i < NCTA * 64) g_flag[i] = 0u;
}

// ---------------- Phase 1: xg = x' @ w_ih^T + b_ih + b_hh ----------------
// M=16384 (m = t*32+b), N=4096, K=1024. BM=128, BN=64, BK=32, 256 thr.
// smem floats: A[2][128][36] then B[2][64][36]; pad 36 => conflict-free frag LDS.

__device__ __forceinline__ void p1_load(uint32_t sb, int s, int m0, int n0, int k0, int tid) {
    #pragma unroll
    for (int i = 0; i < 4; i++) {
        int ch = tid + i * 256;
        int row = ch >> 3, cq = ch & 7;
        uint32_t so = sb + (uint32_t)((s * 4608 + row * 36 + cq * 4) * 4);
        const float* gp = g_xr + (size_t)(m0 + row) * HID + k0 + cq * 4;
        asm volatile("cp.async.cg.shared.global [%0], [%1], 16;" :: "r"(so), "l"(gp));
    }
    #pragma unroll
    for (int i = 0; i < 2; i++) {
        int ch = tid + i * 256;
        int row = ch >> 3, cq = ch & 7;
        uint32_t so = sb + (uint32_t)((9216 + s * 2304 + row * 36 + cq * 4) * 4);
        const float* gp = g_wr + (size_t)(n0 + row) * HID + k0 + cq * 4;
        asm volatile("cp.async.cg.shared.global [%0], [%1], 16;" :: "r"(so), "l"(gp));
    }
    asm volatile("cp.async.commit_group;" ::: "memory");
}

__global__ void __launch_bounds__(256) k_gemm(const float* __restrict__ bih,
                                              const float* __restrict__ bhh) {
    extern __shared__ float sm[];
    const int tid  = threadIdx.x;
    const int lane = tid & 31, w = tid >> 5;
    const int wm = w >> 1, wn = w & 1;
    const int g = lane >> 2, tg = lane & 3;
    const int m0 = blockIdx.x * 128;
    const int n0 = blockIdx.y * 64;
    uint32_t sb = (uint32_t)__cvta_generic_to_shared(sm);

    float acc[2][4][4];
    #pragma unroll
    for (int mt = 0; mt < 2; mt++)
        #pragma unroll
        for (int nt = 0; nt < 4; nt++)
            #pragma unroll
            for (int r = 0; r < 4; r++) acc[mt][nt][r] = 0.f;

    p1_load(sb, 0, m0, n0, 0, tid);
    int s = 0;
    for (int it = 0; it < 32; ++it) {
        if (it + 1 < 32) p1_load(sb, s ^ 1, m0, n0, (it + 1) * 32, tid);
        else asm volatile("cp.async.commit_group;" ::: "memory");
        asm volatile("cp.async.wait_group 1;" ::: "memory");
        __syncthreads();

        const unsigned* A = (const unsigned*)(sm + s * 4608);
        const unsigned* B = (const unsigned*)(sm + 9216 + s * 2304);
        #pragma unroll
        for (int ks = 0; ks < 4; ks++) {
            unsigned a[2][4], bf[4][2];
            #pragma unroll
            for (int mt = 0; mt < 2; mt++) {
                int r = wm * 32 + mt * 16 + g;
                int col = ks * 8 + tg;
                a[mt][0] = A[r * 36 + col];
                a[mt][1] = A[(r + 8) * 36 + col];
                a[mt][2] = A[r * 36 + col + 4];
                a[mt][3] = A[(r + 8) * 36 + col + 4];
            }
            #pragma unroll
            for (int nt = 0; nt < 4; nt++) {
                int r = wn * 32 + nt * 8 + g;
                int col = ks * 8 + tg;
                bf[nt][0] = B[r * 36 + col];
                bf[nt][1] = B[r * 36 + col + 4];
            }
            #pragma unroll
            for (int mt = 0; mt < 2; mt++)
                #pragma unroll
                for (int nt = 0; nt < 4; nt++)
                    mma8(acc[mt][nt], a[mt], bf[nt]);
        }
        __syncthreads();
        s ^= 1;
    }

    // epilogue: add biases, store to g_xg[m][n]
    #pragma unroll
    for (int mt = 0; mt < 2; mt++) {
        #pragma unroll
        for (int nt = 0; nt < 4; nt++) {
            int n = n0 + wn * 32 + nt * 8 + 2 * tg;
            float b0 = bih[n] + bhh[n];
            float b1 = bih[n + 1] + bhh[n + 1];
            int ma = m0 + wm * 32 + mt * 16 + g;
            float2 v0 = make_float2(acc[mt][nt][0] + b0, acc[mt][nt][1] + b1);
            float2 v1 = make_float2(acc[mt][nt][2] + b0, acc[mt][nt][3] + b1);
            *(float2*)&g_xg[(size_t)ma * NG + n]       = v0;
            *(float2*)&g_xg[(size_t)(ma + 8) * NG + n] = v1;
        }
    }
}

// ---------------- Phase 2: persistent recurrence (v5) ----------------
// 128 CTAs x 256 threads, 1 CTA/SM. CTA j owns hidden n0=j*8..j*8+7.
// w_hh fragments in REGISTERS. NO global barrier: per-producer epoch flags.
// Warp w consumes h columns [w*128, w*128+128) produced by CTAs w*16..w*16+15;
// lanes 0-15 ld.acquire-spin on those 16 flags, then warp-private cp.async
// staging (4 commit groups of 8 rows) overlapped with tf32 mma halves.
// h triple-buffered (D=3 closes the 1-step-lead WAR window).
// smem floats: hbuf[8][32][132] (135168 B) then red[8][32][36] (36864 B).

#define P2_HALF(nt0)                                                        \
    _Pragma("unroll")                                                       \
    for (int ks = 0; ks < 16; ++ks) {                                       \
        int k0 = ks * 8 + tg;                                               \
        unsigned bf0[2], bf1[2];                                            \
        bf0[0] = hw[((nt0) * 8 + g) * 132 + k0];                            \
        bf0[1] = hw[((nt0) * 8 + g) * 132 + k0 + 4];                        \
        bf1[0] = hw[((nt0) * 8 + 8 + g) * 132 + k0];                        \
        bf1[1] = hw[((nt0) * 8 + 8 + g) * 132 + k0 + 4];                    \
        mma8(acc[0][(nt0)], a[ks][0], bf0);                                 \
        mma8(acc[1][(nt0)], a[ks][1], bf0);                                 \
        mma8(acc[0][(nt0) + 1], a[ks][0], bf1);                             \
        mma8(acc[1][(nt0) + 1], a[ks][1], bf1);                             \
    }

__global__ void __launch_bounds__(256) k_recur(const float* __restrict__ whh,
                                               float* __restrict__ out) {
    extern __shared__ float sm[];
    float* red = sm + 8 * 32 * 132;   // after per-warp h buffers
    const int tid  = threadIdx.x;
    const int lane = tid & 31, w = tid >> 5;
    const int g = lane >> 2, tg = lane & 3;
    const int n0 = blockIdx.x * 8;
    const int kw = w * 128;           // this warp's K slice
    const int j0 = w * 16;            // first producer CTA of this slice
    const int eb = tid >> 3;          // batch index for epilogue
    const int en = tid & 7;           // local hidden index for epilogue

    float* hbw = sm + w * 32 * 132;   // this warp's private h slice buffer
    uint32_t hb = (uint32_t)__cvta_generic_to_shared(hbw);
    const unsigned* hw = (const unsigned*)hbw;

    // Load this thread's w_hh A-fragments once; resident for all 512 steps.
    unsigned a[16][2][4];
    #pragma unroll
    for (int ks = 0; ks < 16; ks++) {
        #pragma unroll
        for (int mt = 0; mt < 2; mt++) {
            int r0 = mt * 16 + g;
            int r1 = r0 + 8;
            size_t row0 = (size_t)((r0 >> 3) * HID + n0 + (r0 & 7)) * HID;
            size_t row1 = (size_t)((r1 >> 3) * HID + n0 + (r1 & 7)) * HID;
            int k0 = kw + ks * 8 + tg;
            a[ks][mt][0] = __float_as_uint(tf32r(whh[row0 + k0]));
            a[ks][mt][1] = __float_as_uint(tf32r(whh[row1 + k0]));
            a[ks][mt][2] = __float_as_uint(tf32r(whh[row0 + k0 + 4]));
            a[ks][mt][3] = __float_as_uint(tf32r(whh[row1 + k0 + 4]));
        }
    }

    float c = 0.f;

    for (int t = 0; t < TT; ++t) {
        // prefetch input-gate values first (independent of flags; hides DRAM lat)
        const float* xp = g_xg + ((size_t)t * 32 + eb) * NG + n0 + en;
        float xi  = __ldcs(xp);
        float xf  = __ldcs(xp + 1024);
        float xgt = __ldcs(xp + 2048);
        float xo  = __ldcs(xp + 3072);

        // wait for this warp's 16 producers to publish h for step t
        if (lane < 16) {
            const unsigned* fp = g_flag + (j0 + lane) * 64;
            unsigned v;
            do {
                asm volatile("ld.acquire.gpu.global.u32 %0, [%1];"
                             : "=r"(v) : "l"(fp) : "memory");
            } while (v < (unsigned)t);
        }
        __syncwarp();

        const float* __restrict__ hcur = g_h[t % 3];

        // stage this warp's K-slice of h: 4 commit groups of 8 rows
        #pragma unroll
        for (int q = 0; q < 4; q++) {
            #pragma unroll
            for (int j = 0; j < 8; j++) {
                int r = q * 8 + j;
                uint32_t so = hb + (uint32_t)((r * 132 + lane * 4) * 4);
                const float* gp = hcur + r * HID + kw + lane * 4;
                asm volatile("cp.async.cg.shared.global [%0], [%1], 16;" :: "r"(so), "l"(gp));
            }
            asm volatile("cp.async.commit_group;" ::: "memory");
        }

        float acc[2][4][4];
        #pragma unroll
        for (int mt = 0; mt < 2; mt++)
            #pragma unroll
            for (int nt = 0; nt < 4; nt++)
                #pragma unroll
                for (int r = 0; r < 4; r++) acc[mt][nt][r] = 0.f;

        asm volatile("cp.async.wait_group 2;" ::: "memory");  // rows 0-15 ready
        __syncwarp();
        P2_HALF(0)
        asm volatile("cp.async.wait_group 0;" ::: "memory");  // rows 16-31 ready
        __syncwarp();
        P2_HALF(2)

        // D[r][b] partials -> smem (float2, pad 36)
        #pragma unroll
        for (int mt = 0; mt < 2; mt++) {
            #pragma unroll
            for (int nt = 0; nt < 4; nt++) {
                int r = mt * 16 + g, b = nt * 8 + 2 * tg;
                *(float2*)&red[(w * 32 + r) * 36 + b]     = make_float2(acc[mt][nt][0], acc[mt][nt][1]);
                *(float2*)&red[(w * 32 + r + 8) * 36 + b] = make_float2(acc[mt][nt][2], acc[mt][nt][3]);
            }
        }
        __syncthreads();

        // reduce 8 warps + cell update (thread -> (eb, en)); reads conflict-free
        float si = 0.f, sf = 0.f, sg = 0.f, so = 0.f;
        #pragma unroll
        for (int ww = 0; ww < 8; ww++) {
            si += red[(ww * 32 + en) * 36 + eb];
            sf += red[(ww * 32 + 8 + en) * 36 + eb];
            sg += red[(ww * 32 + 16 + en) * 36 + eb];
            so += red[(ww * 32 + 24 + en) * 36 + eb];
        }
        float gi = sigm(si + xi);
        float gf = sigm(sf + xf);
        float gg = tanhf(sg + xgt);
        float go = sigm(so + xo);
        c = gf * c + gi * gg;
        float h = go * tanhf(c);

        g_h[(t + 1) % 3][eb * HID + n0 + en] = tf32r(h);
        if (t == TT - 1) out[eb * HID + n0 + en] = h;

        // publish: all 256 h stores done -> one release store of this CTA's flag
        __syncthreads();
        if (tid == 0) {
            asm volatile("st.release.gpu.global.u32 [%0], %1;"
                         :: "l"(g_flag + blockIdx.x * 64), "r"((unsigned)(t + 1)) : "memory");
        }
    }
}

// ---------------- launch ----------------
extern "C" void kernel_launch(void* const* d_in, const int* in_sizes, int n_in,
                              void* d_out, int out_size) {
    const float* x   = (const float*)d_in[0];
    const float* wih = (const float*)d_in[1];
    const float* whh = (const float*)d_in[2];
    const float* bih = (const float*)d_in[3];
    const float* bhh = (const float*)d_in[4];
    float* out = (float*)d_out;

    cudaFuncSetAttribute(k_gemm,  cudaFuncAttributeMaxDynamicSharedMemorySize, 55296);
    cudaFuncSetAttribute(k_recur, cudaFuncAttributeMaxDynamicSharedMemorySize, 172032);

    k_prep<<<20480, 256>>>((const float4*)x, (const float4*)wih);
    k_init<<<128, 256>>>();

    dim3 gg(128, 64);
    k_gemm<<<gg, 256, 55296>>>(bih, bhh);
    k_recur<<<NCTA, 256, 172032>>>(whh, out);
}